// round 15
// baseline (speedup 1.0000x reference)
#include <cuda_runtime.h>
#include <cuda_bf16.h>
#include <cstdint>
#include <cstddef>

// ---------------- problem dims ----------------
#define S_LEN 512
#define B_SZ  64
#define H_SZ  1024
#define M_ROWS (S_LEN * B_SZ)   // 32768
#define N_J    (2 * H_SZ)       // 2048
#define K_DIM  H_SZ             // 1024

// ---------------- device scratch (no allocs allowed) ----------------
__device__ __align__(128) __nv_bfloat16 g_enc[(size_t)M_ROWS * K_DIM]; // 64 MB
__device__ __align__(128) __nv_bfloat16 g_Wb[(size_t)N_J * K_DIM];     // 4 MB
__device__ __align__(128) float g_hb[N_J * B_SZ];                      // [j][b]
__device__ __align__(128) float g_sc[B_SZ * S_LEN];                    // [b][s] raw scores

// ---------------- helpers ----------------
static __device__ __forceinline__ uint32_t smem_u32(const void* p) {
    uint32_t a;
    asm("{ .reg .u64 t; cvta.to.shared.u64 t, %1; cvt.u32.u64 %0, t; }" : "=r"(a) : "l"(p));
    return a;
}

static __device__ __forceinline__ void cp_async16(uint32_t dst, const void* src) {
    asm volatile("cp.async.cg.shared.global [%0], [%1], 16;" :: "r"(dst), "l"(src));
}

static __device__ __forceinline__ void ldsm4(uint32_t addr, uint32_t& r0, uint32_t& r1,
                                             uint32_t& r2, uint32_t& r3) {
    asm volatile("ldmatrix.sync.aligned.m8n8.x4.shared.b16 {%0,%1,%2,%3}, [%4];"
                 : "=r"(r0), "=r"(r1), "=r"(r2), "=r"(r3) : "r"(addr));
}

static __device__ __forceinline__ void mma16816(float* c, const uint32_t* a,
                                                uint32_t b0, uint32_t b1) {
    asm volatile(
        "mma.sync.aligned.m16n8k16.row.col.f32.bf16.bf16.f32 "
        "{%0,%1,%2,%3}, {%4,%5,%6,%7}, {%8,%9}, {%0,%1,%2,%3};"
        : "+f"(c[0]), "+f"(c[1]), "+f"(c[2]), "+f"(c[3])
        : "r"(a[0]), "r"(a[1]), "r"(a[2]), "r"(a[3]), "r"(b0), "r"(b1));
}

static __device__ __forceinline__ float tanh_fast(float x) {
    float y;
    asm("tanh.approx.f32 %0, %1;" : "=f"(y) : "f"(x));
    return y;
}

// swizzled byte offset inside a [rows][64 bf16] tile (128B rows, 8x16B chunks)
static __device__ __forceinline__ uint32_t sw_off(int row, int chunk) {
    return (uint32_t)(row * 128 + ((chunk ^ (row & 7)) << 4));
}

// ============= K1: fp32 -> bf16 conversion (enc + W_attn[:,H:2H]) =============
static __device__ __forceinline__ void st_bf16x4(__nv_bfloat16* dst, float4 v) {
    __nv_bfloat162 lo = __floats2bfloat162_rn(v.x, v.y);
    __nv_bfloat162 hi = __floats2bfloat162_rn(v.z, v.w);
    uint2 u;
    u.x = *reinterpret_cast<uint32_t*>(&lo);
    u.y = *reinterpret_cast<uint32_t*>(&hi);
    *reinterpret_cast<uint2*>(dst) = u;
}

__global__ void k_convert(const float* __restrict__ enc, const float* __restrict__ W) {
    const int64_t nEnc4 = (int64_t)M_ROWS * K_DIM / 4;
    const int64_t nW4   = (int64_t)N_J * K_DIM / 4;
    const float4* e4 = reinterpret_cast<const float4*>(enc);
    const float4* w4 = reinterpret_cast<const float4*>(W);
    int64_t stride = (int64_t)gridDim.x * blockDim.x;
    for (int64_t p = (int64_t)blockIdx.x * blockDim.x + threadIdx.x;
         p < nEnc4 + nW4; p += stride) {
        if (p < nEnc4) {
            st_bf16x4(g_enc + p * 4, e4[p]);
        } else {
            int64_t q = p - nEnc4;
            int64_t j = q >> 8;
            int64_t kk = q & 255;
            st_bf16x4(g_Wb + j * 1024 + kk * 4, w4[j * 512 + 256 + kk]);
        }
    }
}

// dummy launches so the profiled slot (launch index 3) lands on k_hidbias
__global__ void k_nop() {}

// ============= K2: hb[j][b] = b_attn[j] + hidden[b,:] . W_attn[j,0:H] =============
// 128 blocks x 512 threads: 4 k-slices of 256 (8 serial tiles each).
// Per slice 128 threads; each thread: 2 j x 4 b (6 LDS per 8 FMA).
// smem: sW[4][16][33] + sH[4][64][33] = 42.2 KB; sred aliased on top.
__global__ void __launch_bounds__(512, 2)
k_hidbias(const float* __restrict__ hidden, const float* __restrict__ W,
          const float* __restrict__ b_attn) {
    __shared__ float smem_f[10560];          // 42240 B
    float* sW = smem_f;                      // [4][16][33] : ks*528 + r*33 + c
    float* sH = smem_f + 2112;               // [4][64][33] : ks*2112 + r*33 + c
    float* sred = smem_f;                    // alias, used after final sync: 3*128*8

    const int tid = threadIdx.x;
    const int ks = tid >> 7;        // k-slice 0..3
    const int stid = tid & 127;
    const int j0 = blockIdx.x * 16;
    const int tj = stid >> 4;       // j pair index 0..7
    const int tb = stid & 15;       // b base: tb, tb+16, tb+32, tb+48
    const int kbase = ks * 256;
    float acc[2][4] = {{0.f,0.f,0.f,0.f},{0.f,0.f,0.f,0.f}};

    for (int k0 = 0; k0 < 256; k0 += 32) {
        __syncthreads();
        #pragma unroll
        for (int i = 0; i < 4; i++) {
            int idx = stid + i * 128; int r = idx >> 5, c = idx & 31;
            sW[ks * 528 + r * 33 + c] = W[(size_t)(j0 + r) * 2048 + kbase + k0 + c];
        }
        #pragma unroll
        for (int i = 0; i < 16; i++) {
            int idx = stid + i * 128; int r = idx >> 5, c = idx & 31;
            sH[ks * 2112 + r * 33 + c] = hidden[r * 1024 + kbase + k0 + c];
        }
        __syncthreads();
        const float* wrow0 = sW + ks * 528 + (tj * 2) * 33;
        const float* wrow1 = wrow0 + 33;
        const float* hbase = sH + ks * 2112;
        #pragma unroll
        for (int kk = 0; kk < 32; kk++) {
            float w0 = wrow0[kk], w1 = wrow1[kk];
            float h0 = hbase[tb * 33 + kk];
            float h1 = hbase[(tb + 16) * 33 + kk];
            float h2 = hbase[(tb + 32) * 33 + kk];
            float h3 = hbase[(tb + 48) * 33 + kk];
            acc[0][0] = fmaf(w0, h0, acc[0][0]); acc[0][1] = fmaf(w0, h1, acc[0][1]);
            acc[0][2] = fmaf(w0, h2, acc[0][2]); acc[0][3] = fmaf(w0, h3, acc[0][3]);
            acc[1][0] = fmaf(w1, h0, acc[1][0]); acc[1][1] = fmaf(w1, h1, acc[1][1]);
            acc[1][2] = fmaf(w1, h2, acc[1][2]); acc[1][3] = fmaf(w1, h3, acc[1][3]);
        }
    }
    __syncthreads();   // everyone done reading sW/sH; safe to alias sred
    if (ks != 0) {
        int base = ((ks - 1) * 128 + stid) * 8;
        #pragma unroll
        for (int jj = 0; jj < 2; jj++)
            #pragma unroll
            for (int q = 0; q < 4; q++)
                sred[base + jj * 4 + q] = acc[jj][q];
    }
    __syncthreads();
    if (ks == 0) {
        #pragma unroll
        for (int jj = 0; jj < 2; jj++) {
            int j = j0 + tj * 2 + jj;
            float bj = b_attn[j];
            #pragma unroll
            for (int q = 0; q < 4; q++) {
                float v = acc[jj][q];
                #pragma unroll
                for (int sl = 0; sl < 3; sl++)
                    v += sred[(sl * 128 + stid) * 8 + jj * 4 + q];
                g_hb[j * 64 + tb + 16 * q] = v + bj;
            }
        }
    }
}

// ============= K3: fused GEMM + tanh + score reduction (unchanged, best known) =============
#define BM 128
#define BN 128
#define BK 64
#define NCHUNK 256   // 16 nt * 16 ks
// dynamic smem: A stages @ 0/16384/32768 ; B stages @ 49152/65536/81920 ; total 98304
__global__ void __launch_bounds__(256, 2)
k_gemm_scores(const float* __restrict__ W2) {
    extern __shared__ __align__(1024) char smem[];
    __shared__ float sScore[BM];
    const uint32_t sbase = smem_u32(smem);

    const int tid = threadIdx.x;
    const int m0 = blockIdx.x * BM;
    if (tid < BM) sScore[tid] = 0.f;

    const int warp = tid >> 5, lane = tid & 31;
    const int wm = (warp >> 2) * 64;  // 2 M-warps * 64 rows
    const int wn = (warp & 3) * 32;   // 4 N-warps * 32 cols

    const int aRow0 = wm + (lane & 15);
    const int aChA  = lane >> 4;
    const int bRow0 = wn + ((lane >> 4) << 3) + (lane & 7);
    const int bChA  = (lane >> 3) & 1;

    const int g = lane >> 2, lam = lane & 3;
    float racc[8];
    #pragma unroll
    for (int i = 0; i < 8; i++) racc[i] = 0.f;

    const __nv_bfloat16* gA = g_enc + (size_t)m0 * K_DIM;

    int ldStage = 0;  // stage for next load_chunk call
    auto load_chunk = [&](int c) {
        int nt = c >> 4, ks = c & 15;
        const __nv_bfloat16* srcA = gA + ks * 64;
        uint32_t dA = sbase + ldStage * 16384;
        #pragma unroll
        for (int i = 0; i < 4; i++) {
            int idx = tid + i * 256; int row = idx >> 3, ch = idx & 7;
            cp_async16(dA + sw_off(row, ch), srcA + row * K_DIM + ch * 8);
        }
        const __nv_bfloat16* srcB = g_Wb + (size_t)nt * BN * K_DIM + ks * 64;
        uint32_t dB = sbase + 49152 + ldStage * 16384;
        #pragma unroll
        for (int i = 0; i < 4; i++) {
            int idx = tid + i * 256; int row = idx >> 3, ch = idx & 7;
            cp_async16(dB + sw_off(row, ch), srcB + row * K_DIM + ch * 8);
        }
        asm volatile("cp.async.commit_group;");
        if (++ldStage == 3) ldStage = 0;
    };

    float acc[4][4][4];
    load_chunk(0);
    load_chunk(1);

    int cStage = 0;  // compute stage
    for (int c = 0; c < NCHUNK; c++) {
        const int ks = c & 15, nt = c >> 4;
        if (ks == 0) {
            #pragma unroll
            for (int i = 0; i < 4; i++)
                #pragma unroll
                for (int j = 0; j < 4; j++)
                    #pragma unroll
                    for (int e = 0; e < 4; e++) acc[i][j][e] = 0.f;
        }

        if (c == NCHUNK - 1) asm volatile("cp.async.wait_group 0;");
        else                 asm volatile("cp.async.wait_group 1;");
        __syncthreads();   // chunk c visible; all done reading the stage about to be reloaded

        if (c + 2 < NCHUNK) load_chunk(c + 2);

        const uint32_t bA = sbase + cStage * 16384;
        const uint32_t bB = sbase + 49152 + cStage * 16384;
        if (++cStage == 3) cStage = 0;

        #pragma unroll
        for (int k16 = 0; k16 < 4; k16++) {
            uint32_t a[4][4];
            #pragma unroll
            for (int mi = 0; mi < 4; mi++)
                ldsm4(bA + sw_off(aRow0 + mi * 16, k16 * 2 + aChA),
                      a[mi][0], a[mi][1], a[mi][2], a[mi][3]);
            uint32_t b[2][4];
            #pragma unroll
            for (int ni = 0; ni < 2; ni++)
                ldsm4(bB + sw_off(bRow0 + ni * 16, k16 * 2 + bChA),
                      b[ni][0], b[ni][1], b[ni][2], b[ni][3]);
            #pragma unroll
            for (int mi = 0; mi < 4; mi++)
                #pragma unroll
                for (int ns = 0; ns < 4; ns++) {
                    int ni = ns >> 1, h = (ns & 1) * 2;
                    mma16816(acc[mi][ns], a[mi], b[ni][h], b[ni][h + 1]);
                }
        }

        if (ks == 15) {
            // epilogue for tile nt: tanh(C + hb) * W2 -> per-thread row accumulators
            #pragma unroll
            for (int mi = 0; mi < 4; mi++)
                #pragma unroll
                for (int ns = 0; ns < 4; ns++) {
                    int ncol = nt * BN + wn + ns * 8 + lam * 2;
                    #pragma unroll
                    for (int e = 0; e < 4; e++) {
                        int r = wm + mi * 16 + g + ((e >> 1) << 3);
                        int n = ncol + (e & 1);
                        float x = acc[mi][ns][e] + __ldg(&g_hb[n * 64 + (r & 63)]);
                        racc[mi * 2 + (e >> 1)] =
                            fmaf(tanh_fast(x), __ldg(&W2[n]), racc[mi * 2 + (e >> 1)]);
                    }
                }
        }
    }

    // reduce over lane quads (lanes sharing rows), then across N-warps via smem
    #pragma unroll
    for (int i = 0; i < 8; i++) {
        racc[i] += __shfl_xor_sync(0xffffffffu, racc[i], 1);
        racc[i] += __shfl_xor_sync(0xffffffffu, racc[i], 2);
    }
    if (lam == 0) {
        #pragma unroll
        for (int mi = 0; mi < 4; mi++)
            #pragma unroll
            for (int hi = 0; hi < 2; hi++)
                atomicAdd(&sScore[wm + mi * 16 + hi * 8 + g], racc[mi * 2 + hi]);
    }
    __syncthreads();
    if (tid < BM) {
        int m = m0 + tid;
        g_sc[(m & 63) * S_LEN + (m >> 6)] = sScore[tid];
    }
}

// ============= K4: fused softmax + applied (unchanged, best known) =============
// 1024 blocks: b = blk>>4, hc = blk&15 (64 h-cols per block).
__global__ void __launch_bounds__(256)
k_applied(const float* __restrict__ enc, float* __restrict__ applied_out) {
    __shared__ float w[S_LEN];
    __shared__ float red[8];
    __shared__ float part[16][64];
    const int b = blockIdx.x >> 4;
    const int hc = blockIdx.x & 15;
    const int t = threadIdx.x;

    // ---- softmax over g_sc[b][0..512) ----
    float v0 = g_sc[b * S_LEN + t], v1 = g_sc[b * S_LEN + 256 + t];
    float mx = fmaxf(v0, v1);
    #pragma unroll
    for (int o = 16; o > 0; o >>= 1) mx = fmaxf(mx, __shfl_xor_sync(0xffffffffu, mx, o));
    if ((t & 31) == 0) red[t >> 5] = mx;
    __syncthreads();
    float m8 = red[t & 7];
    #pragma unroll
    for (int o = 4; o > 0; o >>= 1) m8 = fmaxf(m8, __shfl_xor_sync(0xffffffffu, m8, o));
    mx = m8;
    float e0 = __expf(v0 - mx), e1 = __expf(v1 - mx);
    float sm = e0 + e1;
    #pragma unroll
    for (int o = 16; o > 0; o >>= 1) sm += __shfl_xor_sync(0xffffffffu, sm, o);
    __syncthreads();
    if ((t & 31) == 0) red[t >> 5] = sm;
    __syncthreads();
    float s8 = red[t & 7];
    #pragma unroll
    for (int o = 4; o > 0; o >>= 1) s8 += __shfl_xor_sync(0xffffffffu, s8, o);
    float inv = __frcp_rn(s8);
    w[t] = e0 * inv;
    w[t + 256] = e1 * inv;
    __syncthreads();

    // ---- applied: 16 s-groups x 16 lanes, float4 per lane ----
    const int sg = t >> 4, l = t & 15;
    const float* base = enc + (size_t)b * H_SZ + hc * 64 + l * 4;
    float4 acc = make_float4(0.f, 0.f, 0.f, 0.f);
    #pragma unroll 8
    for (int ss = sg; ss < S_LEN; ss += 16) {
        float4 e = *reinterpret_cast<const float4*>(base + (size_t)ss * B_SZ * H_SZ);
        float ws = w[ss];
        acc.x = fmaf(ws, e.x, acc.x);
        acc.y = fmaf(ws, e.y, acc.y);
        acc.z = fmaf(ws, e.z, acc.z);
        acc.w = fmaf(ws, e.w, acc.w);
    }
    part[sg][l * 4 + 0] = acc.x;
    part[sg][l * 4 + 1] = acc.y;
    part[sg][l * 4 + 2] = acc.z;
    part[sg][l * 4 + 3] = acc.w;
    __syncthreads();
    if (t < 64) {
        float r = 0.f;
        #pragma unroll
        for (int gq = 0; gq < 16; gq++) r += part[gq][t];
        applied_out[b * H_SZ + hc * 64 + t] = r;
    }
}

// ============= K5: out[b][h] = tanh(cat(dec, applied)[b,:] . Wc[h,:] + bc[h]) =============
// 128 blocks x 512 threads: 4 k-slices of 512 (16 serial tiles each).
// Per slice 128 threads; each thread: 2 h x 2 b (4 LDS per 4 FMA).
// smem: sW[4][8][33] + sX[4][64][33] = 38 KB; sred aliased on top.
__global__ void __launch_bounds__(512, 2)
k_final(const float* __restrict__ dec, const float* __restrict__ Wc,
        const float* __restrict__ bc, const float* __restrict__ applied,
        float* __restrict__ out) {
    __shared__ float smem_f[9504];           // 38016 B
    float* sW = smem_f;                      // [4][8][33]  : ks*264 + r*33 + c
    float* sX = smem_f + 1056;               // [4][64][33] : ks*2112 + r*33 + c
    float* sred = smem_f;                    // alias: 3*128*4

    const int tid = threadIdx.x;
    const int ks = tid >> 7;       // k-slice 0..3
    const int stid = tid & 127;
    const int h0 = blockIdx.x * 8;
    const int th = stid >> 5;      // h pair index 0..3
    const int tb = stid & 31;      // b base: tb, tb+32
    const float* src = (ks < 2) ? dec : applied;
    const int kofs = (ks & 1) * 512;
    float acc[2][2] = {{0.f, 0.f}, {0.f, 0.f}};

    for (int k0 = 0; k0 < 512; k0 += 32) {
        __syncthreads();
        #pragma unroll
        for (int i = 0; i < 2; i++) {
            int idx = stid + i * 128; int r = idx >> 5, c = idx & 31;
            sW[ks * 264 + r * 33 + c] = Wc[(size_t)(h0 + r) * 2048 + ks * 512 + k0 + c];
        }
        #pragma unroll
        for (int i = 0; i < 16; i++) {
            int idx = stid + i * 128; int r = idx >> 5, c = idx & 31;
            sX[ks * 2112 + r * 33 + c] = src[r * 1024 + kofs + k0 + c];
        }
        __syncthreads();
        const float* wrow0 = sW + ks * 264 + (th * 2) * 33;
        const float* wrow1 = wrow0 + 33;
        const float* xbase = sX + ks * 2112;
        #pragma unroll
        for (int kk = 0; kk < 32; kk++) {
            float w0 = wrow0[kk], w1 = wrow1[kk];
            float x0 = xbase[tb * 33 + kk];
            float x1 = xbase[(tb + 32) * 33 + kk];
            acc[0][0] = fmaf(w0, x0, acc[0][0]);
            acc[0][1] = fmaf(w0, x1, acc[0][1]);
            acc[1][0] = fmaf(w1, x0, acc[1][0]);
            acc[1][1] = fmaf(w1, x1, acc[1][1]);
        }
    }
    __syncthreads();   // done reading sW/sX; safe to alias sred
    if (ks != 0) {
        int base = ((ks - 1) * 128 + stid) * 4;
        sred[base + 0] = acc[0][0];
        sred[base + 1] = acc[0][1];
        sred[base + 2] = acc[1][0];
        sred[base + 3] = acc[1][1];
    }
    __syncthreads();
    if (ks == 0) {
        #pragma unroll
        for (int hh = 0; hh < 2; hh++) {
            int h = h0 + th * 2 + hh;
            float bh = bc[h];
            #pragma unroll
            for (int bb = 0; bb < 2; bb++) {
                float v = acc[hh][bb];
                #pragma unroll
                for (int sl = 0; sl < 3; sl++)
                    v += sred[(sl * 128 + stid) * 4 + hh * 2 + bb];
                out[(tb + 32 * bb) * H_SZ + h] = tanhf(v + bh);
            }
        }
    }
}

// ============= launch =============
extern "C" void kernel_launch(void* const* d_in, const int* in_sizes, int n_in,
                              void* d_out, int out_size) {
    const float* hidden  = (const float*)d_in[0];
    const float* dec     = (const float*)d_in[1];
    const float* enc     = (const float*)d_in[2];
    const float* W_attn  = (const float*)d_in[3];
    const float* b_attn  = (const float*)d_in[4];
    const float* W2      = (const float*)d_in[5];
    // d_in[6] = b_attn2: softmax-invariant, unused
    const float* W_comb  = (const float*)d_in[7];
    const float* b_comb  = (const float*)d_in[8];

    float* out = (float*)d_out;               // [64,1024]
    float* applied_out = out + B_SZ * H_SZ;   // [64,1024]

    cudaFuncSetAttribute(k_gemm_scores, cudaFuncAttributeMaxDynamicSharedMemorySize, 98304);

    k_convert<<<2048, 256>>>(enc, W_attn);                        // 0
    k_nop<<<1, 32>>>();                                           // 1
    k_nop<<<1, 32>>>();                                           // 2
    k_hidbias<<<128, 512>>>(hidden, W_attn, b_attn);              // 3  <- profiled
    k_gemm_scores<<<M_ROWS / BM, 256, 98304>>>(W2);               // 4
    k_applied<<<B_SZ * 16, 256>>>(enc, applied_out);              // 5
    k_final<<<128, 512>>>(dec, W_comb, b_comb, applied_out, out); // 6
}

// round 16
// speedup vs baseline: 1.0610x; 1.0610x over previous
#include <cuda_runtime.h>
#include <cuda_bf16.h>
#include <cstdint>
#include <cstddef>

// ---------------- problem dims ----------------
#define S_LEN 512
#define B_SZ  64
#define H_SZ  1024
#define M_ROWS (S_LEN * B_SZ)   // 32768
#define N_J    (2 * H_SZ)       // 2048
#define K_DIM  H_SZ             // 1024

// ---------------- device scratch (no allocs allowed) ----------------
__device__ __align__(128) __nv_bfloat16 g_enc[(size_t)M_ROWS * K_DIM]; // 64 MB
__device__ __align__(128) __nv_bfloat16 g_Wb[(size_t)N_J * K_DIM];     // 4 MB
__device__ __align__(128) float g_hb[N_J * B_SZ];                      // [j][b]
__device__ __align__(128) float g_sc[B_SZ * S_LEN];                    // [b][s] raw scores

// ---------------- helpers ----------------
static __device__ __forceinline__ uint32_t smem_u32(const void* p) {
    uint32_t a;
    asm("{ .reg .u64 t; cvta.to.shared.u64 t, %1; cvt.u32.u64 %0, t; }" : "=r"(a) : "l"(p));
    return a;
}

static __device__ __forceinline__ void cp_async16(uint32_t dst, const void* src) {
    asm volatile("cp.async.cg.shared.global [%0], [%1], 16;" :: "r"(dst), "l"(src));
}

static __device__ __forceinline__ void ldsm4(uint32_t addr, uint32_t& r0, uint32_t& r1,
                                             uint32_t& r2, uint32_t& r3) {
    asm volatile("ldmatrix.sync.aligned.m8n8.x4.shared.b16 {%0,%1,%2,%3}, [%4];"
                 : "=r"(r0), "=r"(r1), "=r"(r2), "=r"(r3) : "r"(addr));
}

static __device__ __forceinline__ void mma16816(float* c, const uint32_t* a,
                                                uint32_t b0, uint32_t b1) {
    asm volatile(
        "mma.sync.aligned.m16n8k16.row.col.f32.bf16.bf16.f32 "
        "{%0,%1,%2,%3}, {%4,%5,%6,%7}, {%8,%9}, {%0,%1,%2,%3};"
        : "+f"(c[0]), "+f"(c[1]), "+f"(c[2]), "+f"(c[3])
        : "r"(a[0]), "r"(a[1]), "r"(a[2]), "r"(a[3]), "r"(b0), "r"(b1));
}

static __device__ __forceinline__ float tanh_fast(float x) {
    float y;
    asm("tanh.approx.f32 %0, %1;" : "=f"(y) : "f"(x));
    return y;
}

// swizzled byte offset inside a [rows][64 bf16] tile (128B rows, 8x16B chunks)
static __device__ __forceinline__ uint32_t sw_off(int row, int chunk) {
    return (uint32_t)(row * 128 + ((chunk ^ (row & 7)) << 4));
}

// ============= K1: fp32 -> bf16 conversion (enc + W_attn[:,H:2H]) =============
static __device__ __forceinline__ void st_bf16x4(__nv_bfloat16* dst, float4 v) {
    __nv_bfloat162 lo = __floats2bfloat162_rn(v.x, v.y);
    __nv_bfloat162 hi = __floats2bfloat162_rn(v.z, v.w);
    uint2 u;
    u.x = *reinterpret_cast<uint32_t*>(&lo);
    u.y = *reinterpret_cast<uint32_t*>(&hi);
    *reinterpret_cast<uint2*>(dst) = u;
}

__global__ void k_convert(const float* __restrict__ enc, const float* __restrict__ W) {
    const int64_t nEnc4 = (int64_t)M_ROWS * K_DIM / 4;
    const int64_t nW4   = (int64_t)N_J * K_DIM / 4;
    const float4* e4 = reinterpret_cast<const float4*>(enc);
    const float4* w4 = reinterpret_cast<const float4*>(W);
    int64_t stride = (int64_t)gridDim.x * blockDim.x;
    for (int64_t p = (int64_t)blockIdx.x * blockDim.x + threadIdx.x;
         p < nEnc4 + nW4; p += stride) {
        if (p < nEnc4) {
            st_bf16x4(g_enc + p * 4, e4[p]);
        } else {
            int64_t q = p - nEnc4;
            int64_t j = q >> 8;
            int64_t kk = q & 255;
            st_bf16x4(g_Wb + j * 1024 + kk * 4, w4[j * 512 + 256 + kk]);
        }
    }
}

// ============= K2: hb[j][b] = b_attn[j] + hidden[b,:] . W_attn[j,0:H] =============
// 128 blocks x 512 threads: 2 k-slices of 512 run concurrently (16 serial tiles
// each instead of 32), private smem buffers, smem reduction at the end.
// [R14 version — best measured: 36.4 us]
__global__ void __launch_bounds__(512, 2)
k_hidbias(const float* __restrict__ hidden, const float* __restrict__ W,
          const float* __restrict__ b_attn) {
    __shared__ float sW[2][16][33];
    __shared__ float sH[2][64][33];
    __shared__ float sred[1024];
    const int tid = threadIdx.x;
    const int ks = tid >> 8;        // k-slice 0/1
    const int stid = tid & 255;
    const int j0 = blockIdx.x * 16;
    const int tx = stid & 15;       // b base: tx, tx+16, tx+32, tx+48
    const int ty = stid >> 4;       // j (one per thread)
    const int kbase = ks * 512;
    float acc[4] = {0.f, 0.f, 0.f, 0.f};

    for (int k0 = 0; k0 < 512; k0 += 32) {
        __syncthreads();
        #pragma unroll
        for (int i = 0; i < 2; i++) {
            int idx = stid + i * 256; int r = idx >> 5, c = idx & 31;
            sW[ks][r][c] = W[(size_t)(j0 + r) * 2048 + kbase + k0 + c];
        }
        #pragma unroll
        for (int i = 0; i < 8; i++) {
            int idx = stid + i * 256; int r = idx >> 5, c = idx & 31;
            sH[ks][r][c] = hidden[r * 1024 + kbase + k0 + c];
        }
        __syncthreads();
        #pragma unroll
        for (int kk = 0; kk < 32; kk++) {
            float wv = sW[ks][ty][kk];
            acc[0] = fmaf(wv, sH[ks][tx][kk],      acc[0]);
            acc[1] = fmaf(wv, sH[ks][tx + 16][kk], acc[1]);
            acc[2] = fmaf(wv, sH[ks][tx + 32][kk], acc[2]);
            acc[3] = fmaf(wv, sH[ks][tx + 48][kk], acc[3]);
        }
    }
    if (ks == 1) {
        #pragma unroll
        for (int q = 0; q < 4; q++) sred[stid * 4 + q] = acc[q];
    }
    __syncthreads();
    if (ks == 0) {
        int j = j0 + ty;
        float bj = b_attn[j];
        #pragma unroll
        for (int q = 0; q < 4; q++)
            g_hb[j * 64 + tx + 16 * q] = acc[q] + sred[stid * 4 + q] + bj;
    }
}

// ============= K3: fused GEMM + tanh + score reduction (unchanged, best known) =============
#define BM 128
#define BN 128
#define BK 64
#define NCHUNK 256   // 16 nt * 16 ks
// dynamic smem: A stages @ 0/16384/32768 ; B stages @ 49152/65536/81920 ; total 98304
__global__ void __launch_bounds__(256, 2)
k_gemm_scores(const float* __restrict__ W2) {
    extern __shared__ __align__(1024) char smem[];
    __shared__ float sScore[BM];
    const uint32_t sbase = smem_u32(smem);

    const int tid = threadIdx.x;
    const int m0 = blockIdx.x * BM;
    if (tid < BM) sScore[tid] = 0.f;

    const int warp = tid >> 5, lane = tid & 31;
    const int wm = (warp >> 2) * 64;  // 2 M-warps * 64 rows
    const int wn = (warp & 3) * 32;   // 4 N-warps * 32 cols

    const int aRow0 = wm + (lane & 15);
    const int aChA  = lane >> 4;
    const int bRow0 = wn + ((lane >> 4) << 3) + (lane & 7);
    const int bChA  = (lane >> 3) & 1;

    const int g = lane >> 2, lam = lane & 3;
    float racc[8];
    #pragma unroll
    for (int i = 0; i < 8; i++) racc[i] = 0.f;

    const __nv_bfloat16* gA = g_enc + (size_t)m0 * K_DIM;

    int ldStage = 0;  // stage for next load_chunk call
    auto load_chunk = [&](int c) {
        int nt = c >> 4, ks = c & 15;
        const __nv_bfloat16* srcA = gA + ks * 64;
        uint32_t dA = sbase + ldStage * 16384;
        #pragma unroll
        for (int i = 0; i < 4; i++) {
            int idx = tid + i * 256; int row = idx >> 3, ch = idx & 7;
            cp_async16(dA + sw_off(row, ch), srcA + row * K_DIM + ch * 8);
        }
        const __nv_bfloat16* srcB = g_Wb + (size_t)nt * BN * K_DIM + ks * 64;
        uint32_t dB = sbase + 49152 + ldStage * 16384;
        #pragma unroll
        for (int i = 0; i < 4; i++) {
            int idx = tid + i * 256; int row = idx >> 3, ch = idx & 7;
            cp_async16(dB + sw_off(row, ch), srcB + row * K_DIM + ch * 8);
        }
        asm volatile("cp.async.commit_group;");
        if (++ldStage == 3) ldStage = 0;
    };

    float acc[4][4][4];
    load_chunk(0);
    load_chunk(1);

    int cStage = 0;  // compute stage
    for (int c = 0; c < NCHUNK; c++) {
        const int ks = c & 15, nt = c >> 4;
        if (ks == 0) {
            #pragma unroll
            for (int i = 0; i < 4; i++)
                #pragma unroll
                for (int j = 0; j < 4; j++)
                    #pragma unroll
                    for (int e = 0; e < 4; e++) acc[i][j][e] = 0.f;
        }

        if (c == NCHUNK - 1) asm volatile("cp.async.wait_group 0;");
        else                 asm volatile("cp.async.wait_group 1;");
        __syncthreads();   // chunk c visible; all done reading the stage about to be reloaded

        if (c + 2 < NCHUNK) load_chunk(c + 2);

        const uint32_t bA = sbase + cStage * 16384;
        const uint32_t bB = sbase + 49152 + cStage * 16384;
        if (++cStage == 3) cStage = 0;

        #pragma unroll
        for (int k16 = 0; k16 < 4; k16++) {
            uint32_t a[4][4];
            #pragma unroll
            for (int mi = 0; mi < 4; mi++)
                ldsm4(bA + sw_off(aRow0 + mi * 16, k16 * 2 + aChA),
                      a[mi][0], a[mi][1], a[mi][2], a[mi][3]);
            uint32_t b[2][4];
            #pragma unroll
            for (int ni = 0; ni < 2; ni++)
                ldsm4(bB + sw_off(bRow0 + ni * 16, k16 * 2 + bChA),
                      b[ni][0], b[ni][1], b[ni][2], b[ni][3]);
            #pragma unroll
            for (int mi = 0; mi < 4; mi++)
                #pragma unroll
                for (int ns = 0; ns < 4; ns++) {
                    int ni = ns >> 1, h = (ns & 1) * 2;
                    mma16816(acc[mi][ns], a[mi], b[ni][h], b[ni][h + 1]);
                }
        }

        if (ks == 15) {
            // epilogue for tile nt: tanh(C + hb) * W2 -> per-thread row accumulators
            #pragma unroll
            for (int mi = 0; mi < 4; mi++)
                #pragma unroll
                for (int ns = 0; ns < 4; ns++) {
                    int ncol = nt * BN + wn + ns * 8 + lam * 2;
                    #pragma unroll
                    for (int e = 0; e < 4; e++) {
                        int r = wm + mi * 16 + g + ((e >> 1) << 3);
                        int n = ncol + (e & 1);
                        float x = acc[mi][ns][e] + __ldg(&g_hb[n * 64 + (r & 63)]);
                        racc[mi * 2 + (e >> 1)] =
                            fmaf(tanh_fast(x), __ldg(&W2[n]), racc[mi * 2 + (e >> 1)]);
                    }
                }
        }
    }

    // reduce over lane quads (lanes sharing rows), then across N-warps via smem
    #pragma unroll
    for (int i = 0; i < 8; i++) {
        racc[i] += __shfl_xor_sync(0xffffffffu, racc[i], 1);
        racc[i] += __shfl_xor_sync(0xffffffffu, racc[i], 2);
    }
    if (lam == 0) {
        #pragma unroll
        for (int mi = 0; mi < 4; mi++)
            #pragma unroll
            for (int hi = 0; hi < 2; hi++)
                atomicAdd(&sScore[wm + mi * 16 + hi * 8 + g], racc[mi * 2 + hi]);
    }
    __syncthreads();
    if (tid < BM) {
        int m = m0 + tid;
        g_sc[(m & 63) * S_LEN + (m >> 6)] = sScore[tid];
    }
}

// ============= K4: fused softmax + applied (unchanged, best known) =============
// 1024 blocks: b = blk>>4, hc = blk&15 (64 h-cols per block).
__global__ void __launch_bounds__(256)
k_applied(const float* __restrict__ enc, float* __restrict__ applied_out) {
    __shared__ float w[S_LEN];
    __shared__ float red[8];
    __shared__ float part[16][64];
    const int b = blockIdx.x >> 4;
    const int hc = blockIdx.x & 15;
    const int t = threadIdx.x;

    // ---- softmax over g_sc[b][0..512) ----
    float v0 = g_sc[b * S_LEN + t], v1 = g_sc[b * S_LEN + 256 + t];
    float mx = fmaxf(v0, v1);
    #pragma unroll
    for (int o = 16; o > 0; o >>= 1) mx = fmaxf(mx, __shfl_xor_sync(0xffffffffu, mx, o));
    if ((t & 31) == 0) red[t >> 5] = mx;
    __syncthreads();
    float m8 = red[t & 7];
    #pragma unroll
    for (int o = 4; o > 0; o >>= 1) m8 = fmaxf(m8, __shfl_xor_sync(0xffffffffu, m8, o));
    mx = m8;
    float e0 = __expf(v0 - mx), e1 = __expf(v1 - mx);
    float sm = e0 + e1;
    #pragma unroll
    for (int o = 16; o > 0; o >>= 1) sm += __shfl_xor_sync(0xffffffffu, sm, o);
    __syncthreads();
    if ((t & 31) == 0) red[t >> 5] = sm;
    __syncthreads();
    float s8 = red[t & 7];
    #pragma unroll
    for (int o = 4; o > 0; o >>= 1) s8 += __shfl_xor_sync(0xffffffffu, s8, o);
    float inv = __frcp_rn(s8);
    w[t] = e0 * inv;
    w[t + 256] = e1 * inv;
    __syncthreads();

    // ---- applied: 16 s-groups x 16 lanes, float4 per lane ----
    const int sg = t >> 4, l = t & 15;
    const float* base = enc + (size_t)b * H_SZ + hc * 64 + l * 4;
    float4 acc = make_float4(0.f, 0.f, 0.f, 0.f);
    #pragma unroll 8
    for (int ss = sg; ss < S_LEN; ss += 16) {
        float4 e = *reinterpret_cast<const float4*>(base + (size_t)ss * B_SZ * H_SZ);
        float ws = w[ss];
        acc.x = fmaf(ws, e.x, acc.x);
        acc.y = fmaf(ws, e.y, acc.y);
        acc.z = fmaf(ws, e.z, acc.z);
        acc.w = fmaf(ws, e.w, acc.w);
    }
    part[sg][l * 4 + 0] = acc.x;
    part[sg][l * 4 + 1] = acc.y;
    part[sg][l * 4 + 2] = acc.z;
    part[sg][l * 4 + 3] = acc.w;
    __syncthreads();
    if (t < 64) {
        float r = 0.f;
        #pragma unroll
        for (int gq = 0; gq < 16; gq++) r += part[gq][t];
        applied_out[b * H_SZ + hc * 64 + t] = r;
    }
}

// ============= K5: out[b][h] = tanh(cat(dec, applied)[b,:] . Wc[h,:] + bc[h]) =============
// 128 blocks x 512 threads: slice 0 = dec-half of k, slice 1 = applied-half,
// run concurrently (32 serial tiles each instead of 64); smem reduction.
// [R14 version — best measured]
__global__ void __launch_bounds__(512, 2)
k_final(const float* __restrict__ dec, const float* __restrict__ Wc,
        const float* __restrict__ bc, const float* __restrict__ applied,
        float* __restrict__ out) {
    __shared__ float sW[2][8][33];
    __shared__ float sX[2][64][33];
    __shared__ float sred[512];
    const int tid = threadIdx.x;
    const int ks = tid >> 8;       // k-slice 0/1
    const int stid = tid & 255;
    const int h0 = blockIdx.x * 8;
    const int tx = stid & 31;      // b base: tx, tx+32
    const int ty = stid >> 5;      // h, [0,8)
    const float* src = (ks == 0) ? dec : applied;
    float acc[2] = {0.f, 0.f};

    for (int k0 = 0; k0 < 1024; k0 += 32) {
        __syncthreads();
        {
            int r = stid >> 5, c = stid & 31;
            sW[ks][r][c] = Wc[(size_t)(h0 + r) * 2048 + ks * 1024 + k0 + c];
        }
        #pragma unroll
        for (int i = 0; i < 8; i++) {
            int idx = stid + i * 256; int r = idx >> 5, c = idx & 31;
            sX[ks][r][c] = src[r * 1024 + k0 + c];
        }
        __syncthreads();
        #pragma unroll
        for (int kk = 0; kk < 32; kk++) {
            float wv = sW[ks][ty][kk];
            acc[0] = fmaf(wv, sX[ks][tx][kk],      acc[0]);
            acc[1] = fmaf(wv, sX[ks][tx + 32][kk], acc[1]);
        }
    }
    if (ks == 1) {
        sred[stid * 2]     = acc[0];
        sred[stid * 2 + 1] = acc[1];
    }
    __syncthreads();
    if (ks == 0) {
        int h = h0 + ty;
        float bh = bc[h];
        out[tx * H_SZ + h]        = tanhf(acc[0] + sred[stid * 2] + bh);
        out[(tx + 32) * H_SZ + h] = tanhf(acc[1] + sred[stid * 2 + 1] + bh);
    }
}

// ============= launch =============
extern "C" void kernel_launch(void* const* d_in, const int* in_sizes, int n_in,
                              void* d_out, int out_size) {
    const float* hidden  = (const float*)d_in[0];
    const float* dec     = (const float*)d_in[1];
    const float* enc     = (const float*)d_in[2];
    const float* W_attn  = (const float*)d_in[3];
    const float* b_attn  = (const float*)d_in[4];
    const float* W2      = (const float*)d_in[5];
    // d_in[6] = b_attn2: softmax-invariant, unused
    const float* W_comb  = (const float*)d_in[7];
    const float* b_comb  = (const float*)d_in[8];

    float* out = (float*)d_out;               // [64,1024]
    float* applied_out = out + B_SZ * H_SZ;   // [64,1024]

    cudaFuncSetAttribute(k_gemm_scores, cudaFuncAttributeMaxDynamicSharedMemorySize, 98304);

    k_convert<<<2048, 256>>>(enc, W_attn);                        // 0
    k_hidbias<<<128, 512>>>(hidden, W_attn, b_attn);              // 1
    k_gemm_scores<<<M_ROWS / BM, 256, 98304>>>(W2);               // 2
    k_applied<<<B_SZ * 16, 256>>>(enc, applied_out);              // 3  <- profiled
    k_final<<<128, 512>>>(dec, W_comb, b_comb, applied_out, out); // 4
}